// round 1
// baseline (speedup 1.0000x reference)
#include <cuda_runtime.h>
#include <math.h>

// DuplicateRemovalLayer: x (B,16,3) fp32 -> out (B,16,3) fp32.
// Groups [0:6),[6:9),[9:12),[12:15) each run duplicate removal with
// threshold 0.05; object j is zeroed iff ANY later object i in its group has
// dR(i,j) < 0.05, where inactive objects (pt<=0) use eta=phi=1e6 sentinels.
// Index 15 (MET) is copied through.
//
// Streaming kernel: 128 threads/block, 128 batches/block staged through
// shared memory (padded stride 49 for conflict-free compute access).
// Coalesced float4 global load/store.

#define BATCHES_PER_BLOCK 128
#define THREADS 128
#define FPB 48                 // floats per batch (16*3)
#define F4PB 12                // float4 per batch
#define PAD 49                 // padded floats per batch in smem

__device__ __forceinline__ bool is_dup(const float* E, const float* P, int i, int j) {
    // ΔR(i,j) < 0.05 with jnp.mod semantics for dphi.
    const float PI_F  = 3.14159265358979323846f;   // rounds to fp32 pi
    const float TWOPI = 6.28318530717958647692f;   // rounds to fp32 2pi
    float deta = E[i] - E[j];
    float d    = P[i] - P[j] + PI_F;
    float m    = fmodf(d, TWOPI);
    if (m < 0.0f) m += TWOPI;                      // python-mod sign convention
    float dphi = m - PI_F;
    float dr   = sqrtf(deta * deta + dphi * dphi);
    return dr < 0.05f;
}

template <int N>
__device__ __forceinline__ void remove_group(const float* E, const float* P,
                                             bool* keep, int start) {
    #pragma unroll
    for (int i = 1; i < N; i++) {
        #pragma unroll
        for (int j = 0; j < N; j++) {
            if (j < i) {
                if (is_dup(E, P, start + i, start + j)) keep[start + j] = false;
            }
        }
    }
}

__global__ __launch_bounds__(THREADS)
void dup_removal_kernel(const float* __restrict__ in, float* __restrict__ out, int B) {
    __shared__ float s[BATCHES_PER_BLOCK * PAD];

    const int batch0 = blockIdx.x * BATCHES_PER_BLOCK;
    const int nbatch = min(BATCHES_PER_BLOCK, B - batch0);
    if (nbatch <= 0) return;
    const int nf4 = nbatch * F4PB;

    const long long fbase = (long long)batch0 * FPB;
    const float4* __restrict__ in4 = (const float4*)(in + fbase);
    float4* __restrict__ out4 = (float4*)(out + fbase);

    // Coalesced staged load: global float4 -> padded smem
    for (int f = threadIdx.x; f < nf4; f += THREADS) {
        float4 v = in4[f];
        int b   = f / F4PB;
        int off = (f % F4PB) * 4;
        float* dst = s + b * PAD + off;
        dst[0] = v.x; dst[1] = v.y; dst[2] = v.z; dst[3] = v.w;
    }
    __syncthreads();

    // One thread per batch: compute keep-masks, write zeros in place
    const int b = threadIdx.x;
    if (b < nbatch) {
        float* p = s + b * PAD;

        float E[15], P[15];
        #pragma unroll
        for (int i = 0; i < 15; i++) {
            bool active = p[i * 3 + 0] > 0.0f;
            E[i] = active ? p[i * 3 + 1] : 1000000.0f;
            P[i] = active ? p[i * 3 + 2] : 1000000.0f;
        }

        bool keep[15];
        #pragma unroll
        for (int i = 0; i < 15; i++) keep[i] = true;

        remove_group<6>(E, P, keep, 0);    // jets
        remove_group<3>(E, P, keep, 6);    // electrons
        remove_group<3>(E, P, keep, 9);    // muons
        remove_group<3>(E, P, keep, 12);   // photons
        // index 15 (MET): always kept

        #pragma unroll
        for (int i = 0; i < 15; i++) {
            if (!keep[i]) {
                p[i * 3 + 0] = 0.0f;
                p[i * 3 + 1] = 0.0f;
                p[i * 3 + 2] = 0.0f;
            }
        }
    }
    __syncthreads();

    // Coalesced staged store: padded smem -> global float4
    for (int f = threadIdx.x; f < nf4; f += THREADS) {
        int b2  = f / F4PB;
        int off = (f % F4PB) * 4;
        const float* src = s + b2 * PAD + off;
        out4[f] = make_float4(src[0], src[1], src[2], src[3]);
    }
}

extern "C" void kernel_launch(void* const* d_in, const int* in_sizes, int n_in,
                              void* d_out, int out_size) {
    const float* x = (const float*)d_in[0];
    float* out = (float*)d_out;
    const int B = in_sizes[0] / FPB;
    const int grid = (B + BATCHES_PER_BLOCK - 1) / BATCHES_PER_BLOCK;
    dup_removal_kernel<<<grid, THREADS>>>(x, out, B);
}